// round 2
// baseline (speedup 1.0000x reference)
#include <cuda_runtime.h>
#include <cstdint>

#define NN   100000
#define NE   3200000
#define FH   128
#define FIN  100
#define BNEPS 1e-5f

// ---------------- scratch (static device globals; no allocation) ----------------
__device__ __align__(16) float g_h  [(size_t)NN * FH];   // 51.2 MB  x@W
__device__ __align__(16) float g_agg[(size_t)NN * FH];   // 51.2 MB  GCN output
__device__ int   g_cnt[NN];          // in-degree counts (w/o self loop)
__device__ int   g_off[NN + 1];      // CSR offsets
__device__ int   g_cursor[NN];       // bucket cursors
__device__ int   g_csr[NE];          // 12.8 MB src ids sorted by dst
__device__ float g_isd[NN];          // 1/sqrt(deg)
__device__ float g_sum[FH];
__device__ float g_sumsq[FH];
__device__ __align__(16) float g_A[FH * 2];  // folded BN*Wlin
__device__ float g_base[2];                  // folded bias

// ---------------- K0: zero per-replay state ----------------
__global__ void k_init() {
    int i = blockIdx.x * blockDim.x + threadIdx.x;
    if (i < NN) g_cnt[i] = 0;
    if (i < FH) { g_sum[i] = 0.f; g_sumsq[i] = 0.f; }
}

// ---------------- K1: h = x @ W  (fp32, shared-tiled) ----------------
// block = 128 threads, tile = 16 rows x 128 cols, k-chunks of 50
__global__ void k_gemm(const float* __restrict__ x, const float* __restrict__ W) {
    __shared__ float sW[50 * 128];
    __shared__ float sX[16 * 50];
    int t    = threadIdx.x;
    int row0 = blockIdx.x * 16;
    int half = t >> 6;          // 0..1 -> row group of 8
    int cp   = t & 63;          // column pair
    int c0   = cp * 2;
    float acc[8][2];
#pragma unroll
    for (int r = 0; r < 8; r++) { acc[r][0] = 0.f; acc[r][1] = 0.f; }

    for (int kc = 0; kc < FIN; kc += 50) {
#pragma unroll 10
        for (int k = 0; k < 50; k++) sW[k * 128 + t] = W[(size_t)(kc + k) * 128 + t];
        for (int i = t; i < 16 * 50; i += 128) {
            int r = i / 50, k = i - r * 50;
            sX[i] = x[(size_t)(row0 + r) * FIN + kc + k];
        }
        __syncthreads();
#pragma unroll 10
        for (int k = 0; k < 50; k++) {
            float2 wv = *reinterpret_cast<const float2*>(&sW[k * 128 + c0]);
#pragma unroll
            for (int r = 0; r < 8; r++) {
                float xv = sX[(half * 8 + r) * 50 + k];
                acc[r][0] += xv * wv.x;
                acc[r][1] += xv * wv.y;
            }
        }
        __syncthreads();
    }
#pragma unroll
    for (int r = 0; r < 8; r++) {
        int gr = row0 + half * 8 + r;
        *reinterpret_cast<float2*>(&g_h[(size_t)gr * FH + c0]) =
            make_float2(acc[r][0], acc[r][1]);
    }
}

// ---------------- K2: in-degree counts ----------------
__global__ void k_count(const int* __restrict__ dst) {
    int e = blockIdx.x * blockDim.x + threadIdx.x;
    if (e < NE) atomicAdd(&g_cnt[dst[e]], 1);
}

// ---------------- K3: single-block scan -> CSR offsets, isd, cursor reset ----------------
__global__ void k_scan() {
    __shared__ int sp[1024];
    const int CH = (NN + 1023) / 1024;   // 98
    int t   = threadIdx.x;
    int beg = t * CH;
    int end = min(NN, beg + CH);
    int s = 0;
    for (int i = beg; i < end; i++) s += g_cnt[i];
    sp[t] = s;
    __syncthreads();
    for (int o = 1; o < 1024; o <<= 1) {
        int v = (t >= o) ? sp[t - o] : 0;
        __syncthreads();
        sp[t] += v;
        __syncthreads();
    }
    int run = sp[t] - s;   // exclusive prefix
    for (int i = beg; i < end; i++) {
        g_off[i] = run;
        int c = g_cnt[i];
        run += c;
        g_isd[i]    = rsqrtf((float)(c + 1));   // +1 self loop
        g_cursor[i] = 0;
    }
    if (t == 1023) g_off[NN] = sp[1023];
}

// ---------------- K4: fill CSR buckets ----------------
__global__ void k_fill(const int* __restrict__ src, const int* __restrict__ dst) {
    int e = blockIdx.x * blockDim.x + threadIdx.x;
    if (e < NE) {
        int d = dst[e];
        int p = atomicAdd(&g_cursor[d], 1);
        g_csr[g_off[d] + p] = src[e];
    }
}

// ---------------- K5: warp-per-node gather aggregation + fused BN stats ----------------
__global__ void __launch_bounds__(256) k_agg(const float* __restrict__ b) {
    __shared__ float s1[8][FH];
    __shared__ float s2[8][FH];
    int t = threadIdx.x, w = t >> 5, l = t & 31;

    float4 bv = *reinterpret_cast<const float4*>(&b[4 * l]);

    float sx0 = 0.f, sx1 = 0.f, sx2 = 0.f, sx3 = 0.f;
    float sq0 = 0.f, sq1 = 0.f, sq2 = 0.f, sq3 = 0.f;

    int gw = blockIdx.x * 8 + w;
    int nw = gridDim.x * 8;
    for (int i = gw; i < NN; i += nw) {
        int beg = g_off[i], end = g_off[i + 1];
        float isd_i = g_isd[i];
        float a0 = 0.f, a1 = 0.f, a2 = 0.f, a3 = 0.f;
        for (int base = beg; base < end; base += 32) {
            int idx = base + l;
            int   sv = 0;
            float wv = 0.f;
            if (idx < end) { sv = g_csr[idx]; wv = g_isd[sv] * isd_i; }
            int cnt = min(32, end - base);
            for (int j = 0; j < cnt; j++) {
                int   s  = __shfl_sync(0xffffffffu, sv, j);
                float wj = __shfl_sync(0xffffffffu, wv, j);
                const float4 hv =
                    *reinterpret_cast<const float4*>(&g_h[(size_t)s * FH + 4 * l]);
                a0 += hv.x * wj; a1 += hv.y * wj;
                a2 += hv.z * wj; a3 += hv.w * wj;
            }
        }
        { // self loop
            float wj = isd_i * isd_i;
            const float4 hv =
                *reinterpret_cast<const float4*>(&g_h[(size_t)i * FH + 4 * l]);
            a0 += hv.x * wj; a1 += hv.y * wj;
            a2 += hv.z * wj; a3 += hv.w * wj;
        }
        a0 += bv.x; a1 += bv.y; a2 += bv.z; a3 += bv.w;
        *reinterpret_cast<float4*>(&g_agg[(size_t)i * FH + 4 * l]) =
            make_float4(a0, a1, a2, a3);
        sx0 += a0; sx1 += a1; sx2 += a2; sx3 += a3;
        sq0 += a0 * a0; sq1 += a1 * a1; sq2 += a2 * a2; sq3 += a3 * a3;
    }
    s1[w][4 * l + 0] = sx0; s1[w][4 * l + 1] = sx1;
    s1[w][4 * l + 2] = sx2; s1[w][4 * l + 3] = sx3;
    s2[w][4 * l + 0] = sq0; s2[w][4 * l + 1] = sq1;
    s2[w][4 * l + 2] = sq2; s2[w][4 * l + 3] = sq3;
    __syncthreads();
    if (t < FH) {
        float v = 0.f;
#pragma unroll
        for (int ww = 0; ww < 8; ww++) v += s1[ww][t];
        atomicAdd(&g_sum[t], v);
    } else {
        int c = t - FH;
        float v = 0.f;
#pragma unroll
        for (int ww = 0; ww < 8; ww++) v += s2[ww][c];
        atomicAdd(&g_sumsq[c], v);
    }
}

// ---------------- K6: fold BN into linear layer ----------------
__global__ void k_stats(const float* __restrict__ gamma, const float* __restrict__ beta,
                        const float* __restrict__ Wl,    const float* __restrict__ blin) {
    __shared__ float r0[128], r1[128];
    int c = threadIdx.x;
    float mean   = g_sum[c]   * (1.f / (float)NN);
    float var    = g_sumsq[c] * (1.f / (float)NN) - mean * mean;
    float invstd = rsqrtf(var + BNEPS);
    float scale  = invstd * gamma[c];
    float shift  = beta[c] - mean * scale;
    float w0 = Wl[c * 2 + 0], w1 = Wl[c * 2 + 1];
    g_A[c * 2 + 0] = scale * w0;
    g_A[c * 2 + 1] = scale * w1;
    r0[c] = shift * w0;
    r1[c] = shift * w1;
    __syncthreads();
    for (int o = 64; o; o >>= 1) {
        if (c < o) { r0[c] += r0[c + o]; r1[c] += r1[c + o]; }
        __syncthreads();
    }
    if (c == 0) {
        g_base[0] = blin[0] + r0[0];
        g_base[1] = blin[1] + r1[0];
    }
}

// ---------------- K7: linear + relu + softmax + mask ----------------
// mask is read as int32 (harness promotes numpy bool; nonzero test also
// covers a float32 promotion since 1.0f's bit pattern is nonzero).
__global__ void __launch_bounds__(256) k_final(const int* __restrict__ mask,
                                               float* __restrict__ out) {
    int t = threadIdx.x, w = t >> 5, l = t & 31;
    int i = blockIdx.x * 8 + w;
    if (i >= NN) return;
    const float4 v  = *reinterpret_cast<const float4*>(&g_agg[(size_t)i * FH + 4 * l]);
    const float4 A0 = *reinterpret_cast<const float4*>(&g_A[8 * l]);       // (c,0),(c,1),(c+1,0),(c+1,1)
    const float4 A1 = *reinterpret_cast<const float4*>(&g_A[8 * l + 4]);   // (c+2,..),(c+3,..)
    float p0 = v.x * A0.x + v.y * A0.z + v.z * A1.x + v.w * A1.z;
    float p1 = v.x * A0.y + v.y * A0.w + v.z * A1.y + v.w * A1.w;
#pragma unroll
    for (int o = 16; o; o >>= 1) {
        p0 += __shfl_xor_sync(0xffffffffu, p0, o);
        p1 += __shfl_xor_sync(0xffffffffu, p1, o);
    }
    if (l == 0) {
        float l0 = fmaxf(p0 + g_base[0], 0.f);
        float l1 = fmaxf(p1 + g_base[1], 0.f);
        float m  = fmaxf(l0, l1);
        float e0 = expf(l0 - m);
        float e1 = expf(l1 - m);
        float inv = 1.f / (e0 + e1);
        float mk = (mask[i] != 0) ? 1.f : 0.f;
        *reinterpret_cast<float2*>(&out[(size_t)i * 2]) =
            make_float2(e0 * inv * mk, e1 * inv * mk);
    }
}

// ---------------- launch ----------------
extern "C" void kernel_launch(void* const* d_in, const int* in_sizes, int n_in,
                              void* d_out, int out_size) {
    const float* state = (const float*)d_in[0];   // [N,10,10] -> [N,100]
    const float* W     = (const float*)d_in[1];   // [100,128]
    const float* b     = (const float*)d_in[2];   // [128]
    const float* gamma = (const float*)d_in[3];   // [128]
    const float* beta  = (const float*)d_in[4];   // [128]
    const float* Wlin  = (const float*)d_in[5];   // [128,2]
    const float* blin  = (const float*)d_in[6];   // [2]
    const int*   ei    = (const int*)d_in[7];     // [2,E] row-major
    const int*   mask  = (const int*)d_in[8];     // [N] bool -> int32
    float* out = (float*)d_out;

    const int* src = ei;        // edge_index[0]
    const int* dst = ei + NE;   // edge_index[1]

    k_init <<<(NN + 255) / 256, 256>>>();
    k_gemm <<<NN / 16, 128>>>(state, W);
    k_count<<<(NE + 255) / 256, 256>>>(dst);
    k_scan <<<1, 1024>>>();
    k_fill <<<(NE + 255) / 256, 256>>>(src, dst);
    k_agg  <<<1184, 256>>>(b);
    k_stats<<<1, 128>>>(gamma, beta, Wlin, blin);
    k_final<<<NN / 8, 256>>>(mask, out);
}

// round 4
// speedup vs baseline: 1.6555x; 1.6555x over previous
#include <cuda_runtime.h>
#include <cstdint>

#define NN   100000
#define NE   3200000
#define FH   128
#define FIN  100
#define BNEPS 1e-5f
#define SCAN_BLOCKS ((NN + 1023) / 1024)   // 98

// ---------------- scratch (static device globals; no allocation) ----------------
__device__ __align__(16) float g_h  [(size_t)NN * FH];   // 51.2 MB  x@W
__device__ __align__(16) float g_agg[(size_t)NN * FH];   // 51.2 MB  GCN output
__device__ int   g_cnt[NN];          // in-degree counts (w/o self loop)
__device__ int   g_off[NN + 1];      // CSR offsets
__device__ int   g_cursor[NN];       // bucket cursors
__device__ int   g_csr[NE];          // 12.8 MB src ids sorted by dst
__device__ float g_isd[NN];          // 1/sqrt(deg)
__device__ int   g_bsum[SCAN_BLOCKS];
__device__ int   g_bpre[SCAN_BLOCKS];
__device__ float g_sum[FH];
__device__ float g_sumsq[FH];
__device__ __align__(16) float g_A[FH * 2];  // folded BN*Wlin
__device__ float g_base[2];                  // folded bias

// ---------------- K0: zero per-replay state ----------------
__global__ void k_init() {
    int i = blockIdx.x * blockDim.x + threadIdx.x;
    if (i < NN) g_cnt[i] = 0;
    if (i < FH) { g_sum[i] = 0.f; g_sumsq[i] = 0.f; }
}

// ---------------- K1: h = x @ W  (fp32, shared-tiled) ----------------
__global__ void k_gemm(const float* __restrict__ x, const float* __restrict__ W) {
    __shared__ float sW[50 * 128];
    __shared__ float sX[16 * 50];
    int t    = threadIdx.x;
    int row0 = blockIdx.x * 16;
    int half = t >> 6;          // 0..1 -> row group of 8
    int cp   = t & 63;          // column pair
    int c0   = cp * 2;
    float acc[8][2];
#pragma unroll
    for (int r = 0; r < 8; r++) { acc[r][0] = 0.f; acc[r][1] = 0.f; }

    for (int kc = 0; kc < FIN; kc += 50) {
#pragma unroll 10
        for (int k = 0; k < 50; k++) sW[k * 128 + t] = W[(size_t)(kc + k) * 128 + t];
        for (int i = t; i < 16 * 50; i += 128) {
            int r = i / 50, k = i - r * 50;
            sX[i] = x[(size_t)(row0 + r) * FIN + kc + k];
        }
        __syncthreads();
#pragma unroll 10
        for (int k = 0; k < 50; k++) {
            float2 wv = *reinterpret_cast<const float2*>(&sW[k * 128 + c0]);
#pragma unroll
            for (int r = 0; r < 8; r++) {
                float xv = sX[(half * 8 + r) * 50 + k];
                acc[r][0] += xv * wv.x;
                acc[r][1] += xv * wv.y;
            }
        }
        __syncthreads();
    }
#pragma unroll
    for (int r = 0; r < 8; r++) {
        int gr = row0 + half * 8 + r;
        *reinterpret_cast<float2*>(&g_h[(size_t)gr * FH + c0]) =
            make_float2(acc[r][0], acc[r][1]);
    }
}

// ---------------- K2: in-degree counts ----------------
__global__ void k_count(const int* __restrict__ dst) {
    int e = blockIdx.x * blockDim.x + threadIdx.x;
    if (e < NE) atomicAdd(&g_cnt[dst[e]], 1);
}

// ---------------- K3a: per-block scan of counts (coalesced) + isd + cursor ----------------
__global__ void __launch_bounds__(1024) k_scan1() {
    __shared__ int sp[1024];
    int t = threadIdx.x;
    int i = blockIdx.x * 1024 + t;
    int c = (i < NN) ? g_cnt[i] : 0;
    sp[t] = c;
    __syncthreads();
#pragma unroll
    for (int o = 1; o < 1024; o <<= 1) {
        int v = (t >= o) ? sp[t - o] : 0;
        __syncthreads();
        sp[t] += v;
        __syncthreads();
    }
    if (i < NN) {
        g_off[i]    = sp[t] - c;                 // local exclusive prefix
        g_isd[i]    = rsqrtf((float)(c + 1));    // +1 self loop
        g_cursor[i] = 0;
    }
    if (t == 1023) g_bsum[blockIdx.x] = sp[1023];
}

// ---------------- K3b: scan the 98 block sums ----------------
__global__ void k_scan2() {
    __shared__ int sp[128];
    int t = threadIdx.x;
    int v = (t < SCAN_BLOCKS) ? g_bsum[t] : 0;
    sp[t] = v;
    __syncthreads();
#pragma unroll
    for (int o = 1; o < 128; o <<= 1) {
        int x = (t >= o) ? sp[t - o] : 0;
        __syncthreads();
        sp[t] += x;
        __syncthreads();
    }
    if (t < SCAN_BLOCKS) g_bpre[t] = sp[t] - v;  // exclusive
    if (t == 127) g_off[NN] = sp[127];
}

// ---------------- K3c: add block prefixes ----------------
__global__ void __launch_bounds__(1024) k_scan3() {
    int i = blockIdx.x * 1024 + threadIdx.x;
    if (i < NN) g_off[i] += g_bpre[blockIdx.x];
}

// ---------------- K4: fill CSR buckets ----------------
__global__ void k_fill(const int* __restrict__ src, const int* __restrict__ dst) {
    int e = blockIdx.x * blockDim.x + threadIdx.x;
    if (e < NE) {
        int d = dst[e];
        int p = atomicAdd(&g_cursor[d], 1);
        g_csr[g_off[d] + p] = src[e];
    }
}

// ---------------- K5: warp-per-node gather aggregation + fused BN stats ----------------
__global__ void __launch_bounds__(256) k_agg(const float* __restrict__ b) {
    __shared__ float s1[8][FH];
    __shared__ float s2[8][FH];
    int t = threadIdx.x, w = t >> 5, l = t & 31;

    float4 bv = *reinterpret_cast<const float4*>(&b[4 * l]);

    float sx0 = 0.f, sx1 = 0.f, sx2 = 0.f, sx3 = 0.f;
    float sq0 = 0.f, sq1 = 0.f, sq2 = 0.f, sq3 = 0.f;

    int gw = blockIdx.x * 8 + w;
    int nw = gridDim.x * 8;
    for (int i = gw; i < NN; i += nw) {
        int beg = g_off[i], end = g_off[i + 1];
        float isd_i = g_isd[i];
        float a0 = 0.f, a1 = 0.f, a2 = 0.f, a3 = 0.f;
        for (int base = beg; base < end; base += 32) {
            int idx = base + l;
            int   sv = 0;
            float wv = 0.f;
            if (idx < end) { sv = g_csr[idx]; wv = g_isd[sv] * isd_i; }
            int cnt = min(32, end - base);
            for (int j = 0; j < cnt; j++) {
                int   s  = __shfl_sync(0xffffffffu, sv, j);
                float wj = __shfl_sync(0xffffffffu, wv, j);
                const float4 hv =
                    *reinterpret_cast<const float4*>(&g_h[(size_t)s * FH + 4 * l]);
                a0 += hv.x * wj; a1 += hv.y * wj;
                a2 += hv.z * wj; a3 += hv.w * wj;
            }
        }
        { // self loop
            float wj = isd_i * isd_i;
            const float4 hv =
                *reinterpret_cast<const float4*>(&g_h[(size_t)i * FH + 4 * l]);
            a0 += hv.x * wj; a1 += hv.y * wj;
            a2 += hv.z * wj; a3 += hv.w * wj;
        }
        a0 += bv.x; a1 += bv.y; a2 += bv.z; a3 += bv.w;
        *reinterpret_cast<float4*>(&g_agg[(size_t)i * FH + 4 * l]) =
            make_float4(a0, a1, a2, a3);
        sx0 += a0; sx1 += a1; sx2 += a2; sx3 += a3;
        sq0 += a0 * a0; sq1 += a1 * a1; sq2 += a2 * a2; sq3 += a3 * a3;
    }
    s1[w][4 * l + 0] = sx0; s1[w][4 * l + 1] = sx1;
    s1[w][4 * l + 2] = sx2; s1[w][4 * l + 3] = sx3;
    s2[w][4 * l + 0] = sq0; s2[w][4 * l + 1] = sq1;
    s2[w][4 * l + 2] = sq2; s2[w][4 * l + 3] = sq3;
    __syncthreads();
    if (t < FH) {
        float v = 0.f;
#pragma unroll
        for (int ww = 0; ww < 8; ww++) v += s1[ww][t];
        atomicAdd(&g_sum[t], v);
    } else {
        int c = t - FH;
        float v = 0.f;
#pragma unroll
        for (int ww = 0; ww < 8; ww++) v += s2[ww][c];
        atomicAdd(&g_sumsq[c], v);
    }
}

// ---------------- K6: fold BN into linear layer ----------------
__global__ void k_stats(const float* __restrict__ gamma, const float* __restrict__ beta,
                        const float* __restrict__ Wl,    const float* __restrict__ blin) {
    __shared__ float r0[128], r1[128];
    int c = threadIdx.x;
    float mean   = g_sum[c]   * (1.f / (float)NN);
    float var    = g_sumsq[c] * (1.f / (float)NN) - mean * mean;
    float invstd = rsqrtf(var + BNEPS);
    float scale  = invstd * gamma[c];
    float shift  = beta[c] - mean * scale;
    float w0 = Wl[c * 2 + 0], w1 = Wl[c * 2 + 1];
    g_A[c * 2 + 0] = scale * w0;
    g_A[c * 2 + 1] = scale * w1;
    r0[c] = shift * w0;
    r1[c] = shift * w1;
    __syncthreads();
    for (int o = 64; o; o >>= 1) {
        if (c < o) { r0[c] += r0[c + o]; r1[c] += r1[c + o]; }
        __syncthreads();
    }
    if (c == 0) {
        g_base[0] = blin[0] + r0[0];
        g_base[1] = blin[1] + r1[0];
    }
}

// ---------------- K7: linear + relu + softmax + mask ----------------
__global__ void __launch_bounds__(256) k_final(const int* __restrict__ mask,
                                               float* __restrict__ out) {
    int t = threadIdx.x, w = t >> 5, l = t & 31;
    int i = blockIdx.x * 8 + w;
    if (i >= NN) return;
    const float4 v  = *reinterpret_cast<const float4*>(&g_agg[(size_t)i * FH + 4 * l]);
    const float4 A0 = *reinterpret_cast<const float4*>(&g_A[8 * l]);
    const float4 A1 = *reinterpret_cast<const float4*>(&g_A[8 * l + 4]);
    float p0 = v.x * A0.x + v.y * A0.z + v.z * A1.x + v.w * A1.z;
    float p1 = v.x * A0.y + v.y * A0.w + v.z * A1.y + v.w * A1.w;
#pragma unroll
    for (int o = 16; o; o >>= 1) {
        p0 += __shfl_xor_sync(0xffffffffu, p0, o);
        p1 += __shfl_xor_sync(0xffffffffu, p1, o);
    }
    if (l == 0) {
        float l0 = fmaxf(p0 + g_base[0], 0.f);
        float l1 = fmaxf(p1 + g_base[1], 0.f);
        float m  = fmaxf(l0, l1);
        float e0 = expf(l0 - m);
        float e1 = expf(l1 - m);
        float inv = 1.f / (e0 + e1);
        float mk = (mask[i] != 0) ? 1.f : 0.f;
        *reinterpret_cast<float2*>(&out[(size_t)i * 2]) =
            make_float2(e0 * inv * mk, e1 * inv * mk);
    }
}

// ---------------- launch ----------------
extern "C" void kernel_launch(void* const* d_in, const int* in_sizes, int n_in,
                              void* d_out, int out_size) {
    const float* state = (const float*)d_in[0];
    const float* W     = (const float*)d_in[1];
    const float* b     = (const float*)d_in[2];
    const float* gamma = (const float*)d_in[3];
    const float* beta  = (const float*)d_in[4];
    const float* Wlin  = (const float*)d_in[5];
    const float* blin  = (const float*)d_in[6];
    const int*   ei    = (const int*)d_in[7];
    const int*   mask  = (const int*)d_in[8];
    float* out = (float*)d_out;

    const int* src = ei;        // edge_index[0]
    const int* dst = ei + NE;   // edge_index[1]

    k_init <<<(NN + 255) / 256, 256>>>();
    k_gemm <<<NN / 16, 128>>>(state, W);
    k_count<<<(NE + 255) / 256, 256>>>(dst);
    k_scan1<<<SCAN_BLOCKS, 1024>>>();
    k_scan2<<<1, 128>>>();
    k_scan3<<<SCAN_BLOCKS, 1024>>>();
    k_fill <<<(NE + 255) / 256, 256>>>(src, dst);
    k_agg  <<<1184, 256>>>(b);
    k_stats<<<1, 128>>>(gamma, beta, Wlin, blin);
    k_final<<<NN / 8, 256>>>(mask, out);
}